// round 13
// baseline (speedup 1.0000x reference)
#include <cuda_runtime.h>

#define HID   512
#define NH    16
#define HD    32
#define SEQ   1024
#define BATCH 2
#define MROWS (BATCH*SEQ)   // 2048
#define WIN   128           // gamma^128/(1-gamma) ~ 1.4e-5: safe truncation

// scratch (no allocations allowed)
__device__ float g_q[MROWS*HID];
__device__ float g_k[MROWS*HID];
__device__ float g_v[MROWS*HID];
__device__ float g_att[MROWS*HID];

typedef unsigned long long u64;

#define LOG2G (-0.15200309344504995f)   // log2(0.9)

// ---- packed f32x2 helpers (SASS FFMA2 — only reachable via PTX) ----------
__device__ __forceinline__ u64 pack2(float lo, float hi) {
    u64 r; asm("mov.b64 %0,{%1,%2};" : "=l"(r) : "f"(lo), "f"(hi)); return r;
}
__device__ __forceinline__ float2 unpack2(u64 v) {
    float2 r; asm("mov.b64 {%0,%1},%2;" : "=f"(r.x), "=f"(r.y) : "l"(v)); return r;
}
__device__ __forceinline__ u64 ffma2(u64 a, u64 b, u64 c) {
    u64 d; asm("fma.rn.f32x2 %0,%1,%2,%3;" : "=l"(d) : "l"(a), "l"(b), "l"(c)); return d;
}

// ---------------------------------------------------------------------------
// Fused QKV GEMM: C[M,N] = A @ W + bias, M=2048, N=K=512.
// 128x128 block tile, BK=16, 256 threads, 8x8 scalar microtile = 4 f32x2
// pairs (M) x 8 cols (N). B pre-duplicated as {b,b} u64 pairs in smem.
// Wavefront cost: 8 wf per warp-kk for 32 FFMA2 (0.25 wf/FFMA2) -> fma-bound.
// blockIdx.z selects Q/K/V weight set. smem = 48 KB static.
// ---------------------------------------------------------------------------
__global__ __launch_bounds__(256) void gemm_qkv_kernel(
    const float* __restrict__ A,
    const float* __restrict__ W0, const float* __restrict__ B0, float* __restrict__ C0,
    const float* __restrict__ W1, const float* __restrict__ B1, float* __restrict__ C1,
    const float* __restrict__ W2, const float* __restrict__ B2, float* __restrict__ C2)
{
    const int K = 512, N = 512;
    const float* W = W0; const float* bias = B0; float* C = C0;
    if (blockIdx.z == 1) { W = W1; bias = B1; C = C1; }
    else if (blockIdx.z == 2) { W = W2; bias = B2; C = C2; }

    __shared__ __align__(16) float As[2][16][128];   // 16 KB
    __shared__ __align__(16) u64   Bs[2][16][128];   // 32 KB (duplicated pairs)

    const int tid = threadIdx.x;
    const int m0 = blockIdx.y * 128;
    const int n0 = blockIdx.x * 128;
    const int tr  = tid & 15;        // m-group: 8 rows = 4 pairs
    const int tcg = tid >> 4;        // n-group: 8 cols

    // A load: row = tid>>1 (0..127), k-offset = (tid&1)*8 : 2 float4
    const int ar = tid >> 1;
    const int ak = (tid & 1) * 8;
    // B load: bk = tid>>4 (0..15), bn = (tid&15)*8 : 2 float4
    const int bk = tid >> 4;
    const int bn = (tid & 15) * 8;

    u64 acc[4][8];
    #pragma unroll
    for (int i = 0; i < 4; i++)
        #pragma unroll
        for (int j = 0; j < 8; j++) acc[i][j] = 0ull;

    float4 a0, a1, b0, b1;
    {   // prologue: tile 0
        const float* ap = &A[(size_t)(m0 + ar) * K + ak];
        a0 = *(const float4*)(ap + 0);
        a1 = *(const float4*)(ap + 4);
        b0 = *(const float4*)&W[(size_t)bk * N + n0 + bn];
        b1 = *(const float4*)&W[(size_t)bk * N + n0 + bn + 4];
        As[0][ak+0][ar] = a0.x; As[0][ak+1][ar] = a0.y;
        As[0][ak+2][ar] = a0.z; As[0][ak+3][ar] = a0.w;
        As[0][ak+4][ar] = a1.x; As[0][ak+5][ar] = a1.y;
        As[0][ak+6][ar] = a1.z; As[0][ak+7][ar] = a1.w;
        *(ulonglong2*)&Bs[0][bk][bn]     = make_ulonglong2(pack2(b0.x,b0.x), pack2(b0.y,b0.y));
        *(ulonglong2*)&Bs[0][bk][bn + 2] = make_ulonglong2(pack2(b0.z,b0.z), pack2(b0.w,b0.w));
        *(ulonglong2*)&Bs[0][bk][bn + 4] = make_ulonglong2(pack2(b1.x,b1.x), pack2(b1.y,b1.y));
        *(ulonglong2*)&Bs[0][bk][bn + 6] = make_ulonglong2(pack2(b1.z,b1.z), pack2(b1.w,b1.w));
    }
    __syncthreads();

    for (int k0 = 0; k0 < K; k0 += 16) {
        const int buf = (k0 >> 4) & 1;
        const int nxt = buf ^ 1;
        const bool more = (k0 + 16 < K);
        if (more) {
            const int kn = k0 + 16;
            const float* ap = &A[(size_t)(m0 + ar) * K + kn + ak];
            a0 = *(const float4*)(ap + 0);
            a1 = *(const float4*)(ap + 4);
            b0 = *(const float4*)&W[(size_t)(kn + bk) * N + n0 + bn];
            b1 = *(const float4*)&W[(size_t)(kn + bk) * N + n0 + bn + 4];
        }

        #pragma unroll
        for (int kk = 0; kk < 16; kk++) {
            ulonglong2 al  = *(const ulonglong2*)&As[buf][kk][tr * 8];
            ulonglong2 ah  = *(const ulonglong2*)&As[buf][kk][tr * 8 + 4];
            ulonglong2 b01 = *(const ulonglong2*)&Bs[buf][kk][tcg * 8];
            ulonglong2 b23 = *(const ulonglong2*)&Bs[buf][kk][tcg * 8 + 2];
            ulonglong2 b45 = *(const ulonglong2*)&Bs[buf][kk][tcg * 8 + 4];
            ulonglong2 b67 = *(const ulonglong2*)&Bs[buf][kk][tcg * 8 + 6];
            u64 ap2[4] = {al.x, al.y, ah.x, ah.y};
            u64 bp[8]  = {b01.x, b01.y, b23.x, b23.y, b45.x, b45.y, b67.x, b67.y};
            #pragma unroll
            for (int i = 0; i < 4; i++)
                #pragma unroll
                for (int j = 0; j < 8; j++)
                    acc[i][j] = ffma2(ap2[i], bp[j], acc[i][j]);
        }

        if (more) {
            As[nxt][ak+0][ar] = a0.x; As[nxt][ak+1][ar] = a0.y;
            As[nxt][ak+2][ar] = a0.z; As[nxt][ak+3][ar] = a0.w;
            As[nxt][ak+4][ar] = a1.x; As[nxt][ak+5][ar] = a1.y;
            As[nxt][ak+6][ar] = a1.z; As[nxt][ak+7][ar] = a1.w;
            *(ulonglong2*)&Bs[nxt][bk][bn]     = make_ulonglong2(pack2(b0.x,b0.x), pack2(b0.y,b0.y));
            *(ulonglong2*)&Bs[nxt][bk][bn + 2] = make_ulonglong2(pack2(b0.z,b0.z), pack2(b0.w,b0.w));
            *(ulonglong2*)&Bs[nxt][bk][bn + 4] = make_ulonglong2(pack2(b1.x,b1.x), pack2(b1.y,b1.y));
            *(ulonglong2*)&Bs[nxt][bk][bn + 6] = make_ulonglong2(pack2(b1.z,b1.z), pack2(b1.w,b1.w));
        }
        __syncthreads();
    }

    // epilogue
    float bias8[8];
    #pragma unroll
    for (int j = 0; j < 8; j++) bias8[j] = bias[n0 + tcg * 8 + j];

    #pragma unroll
    for (int p = 0; p < 4; p++) {
        float2 u[8];
        #pragma unroll
        for (int j = 0; j < 8; j++) u[j] = unpack2(acc[p][j]);
        const int row_lo = m0 + tr * 8 + 2 * p;
        float4 lo0 = make_float4(u[0].x + bias8[0], u[1].x + bias8[1],
                                 u[2].x + bias8[2], u[3].x + bias8[3]);
        float4 lo1 = make_float4(u[4].x + bias8[4], u[5].x + bias8[5],
                                 u[6].x + bias8[6], u[7].x + bias8[7]);
        float4 hi0 = make_float4(u[0].y + bias8[0], u[1].y + bias8[1],
                                 u[2].y + bias8[2], u[3].y + bias8[3]);
        float4 hi1 = make_float4(u[4].y + bias8[4], u[5].y + bias8[5],
                                 u[6].y + bias8[6], u[7].y + bias8[7]);
        *(float4*)&C[(size_t)row_lo * N + n0 + tcg * 8]           = lo0;
        *(float4*)&C[(size_t)row_lo * N + n0 + tcg * 8 + 4]       = lo1;
        *(float4*)&C[(size_t)(row_lo + 1) * N + n0 + tcg * 8]     = hi0;
        *(float4*)&C[(size_t)(row_lo + 1) * N + n0 + tcg * 8 + 4] = hi1;
    }
}

// ---------------------------------------------------------------------------
// O-projection GEMM: 128x64 block tile, 256 threads, 2-pair x 8 microtile.
// (128 blocks -> good chip fill for the single trailing GEMM.)
// ---------------------------------------------------------------------------
__global__ __launch_bounds__(256) void gemm_o_kernel(
    const float* __restrict__ A,
    const float* __restrict__ W, const float* __restrict__ bias,
    float* __restrict__ C)
{
    const int K = 512, N = 512;
    __shared__ __align__(16) float As[2][16][128];   // 16 KB
    __shared__ __align__(16) u64   Bs[2][16][64];    // 16 KB (duplicated pairs)

    const int tid = threadIdx.x;
    const int m0 = blockIdx.y * 128;
    const int n0 = blockIdx.x * 64;
    const int tr  = tid & 31;        // m-group: 4 rows = 2 pairs
    const int tcg = tid >> 5;        // n-group: 8 cols (constant per warp)

    const int ar = tid >> 1;
    const int ak = (tid & 1) * 8;
    const int bk = tid >> 4;
    const int bn = (tid & 15) * 4;

    u64 acc[2][8];
    #pragma unroll
    for (int i = 0; i < 2; i++)
        #pragma unroll
        for (int j = 0; j < 8; j++) acc[i][j] = 0ull;

    float4 a0, a1, b0;
    {
        const float* ap = &A[(size_t)(m0 + ar) * K + ak];
        a0 = *(const float4*)(ap + 0);
        a1 = *(const float4*)(ap + 4);
        b0 = *(const float4*)&W[(size_t)bk * N + n0 + bn];
        As[0][ak+0][ar] = a0.x; As[0][ak+1][ar] = a0.y;
        As[0][ak+2][ar] = a0.z; As[0][ak+3][ar] = a0.w;
        As[0][ak+4][ar] = a1.x; As[0][ak+5][ar] = a1.y;
        As[0][ak+6][ar] = a1.z; As[0][ak+7][ar] = a1.w;
        *(ulonglong2*)&Bs[0][bk][bn]     = make_ulonglong2(pack2(b0.x,b0.x), pack2(b0.y,b0.y));
        *(ulonglong2*)&Bs[0][bk][bn + 2] = make_ulonglong2(pack2(b0.z,b0.z), pack2(b0.w,b0.w));
    }
    __syncthreads();

    for (int k0 = 0; k0 < K; k0 += 16) {
        const int buf = (k0 >> 4) & 1;
        const int nxt = buf ^ 1;
        const bool more = (k0 + 16 < K);
        if (more) {
            const int kn = k0 + 16;
            const float* ap = &A[(size_t)(m0 + ar) * K + kn + ak];
            a0 = *(const float4*)(ap + 0);
            a1 = *(const float4*)(ap + 4);
            b0 = *(const float4*)&W[(size_t)(kn + bk) * N + n0 + bn];
        }

        #pragma unroll
        for (int kk = 0; kk < 16; kk++) {
            ulonglong2 a2  = *(const ulonglong2*)&As[buf][kk][tr * 4];
            ulonglong2 b01 = *(const ulonglong2*)&Bs[buf][kk][tcg * 8];
            ulonglong2 b23 = *(const ulonglong2*)&Bs[buf][kk][tcg * 8 + 2];
            ulonglong2 b45 = *(const ulonglong2*)&Bs[buf][kk][tcg * 8 + 4];
            ulonglong2 b67 = *(const ulonglong2*)&Bs[buf][kk][tcg * 8 + 6];
            u64 ap2[2] = {a2.x, a2.y};
            u64 bp[8]  = {b01.x, b01.y, b23.x, b23.y, b45.x, b45.y, b67.x, b67.y};
            #pragma unroll
            for (int i = 0; i < 2; i++)
                #pragma unroll
                for (int j = 0; j < 8; j++)
                    acc[i][j] = ffma2(ap2[i], bp[j], acc[i][j]);
        }

        if (more) {
            As[nxt][ak+0][ar] = a0.x; As[nxt][ak+1][ar] = a0.y;
            As[nxt][ak+2][ar] = a0.z; As[nxt][ak+3][ar] = a0.w;
            As[nxt][ak+4][ar] = a1.x; As[nxt][ak+5][ar] = a1.y;
            As[nxt][ak+6][ar] = a1.z; As[nxt][ak+7][ar] = a1.w;
            *(ulonglong2*)&Bs[nxt][bk][bn]     = make_ulonglong2(pack2(b0.x,b0.x), pack2(b0.y,b0.y));
            *(ulonglong2*)&Bs[nxt][bk][bn + 2] = make_ulonglong2(pack2(b0.z,b0.z), pack2(b0.w,b0.w));
        }
        __syncthreads();
    }

    float bias8[8];
    #pragma unroll
    for (int j = 0; j < 8; j++) bias8[j] = bias[n0 + tcg * 8 + j];

    #pragma unroll
    for (int p = 0; p < 2; p++) {
        float2 u[8];
        #pragma unroll
        for (int j = 0; j < 8; j++) u[j] = unpack2(acc[p][j]);
        const int row_lo = m0 + tr * 4 + 2 * p;
        float4 lo0 = make_float4(u[0].x + bias8[0], u[1].x + bias8[1],
                                 u[2].x + bias8[2], u[3].x + bias8[3]);
        float4 lo1 = make_float4(u[4].x + bias8[4], u[5].x + bias8[5],
                                 u[6].x + bias8[6], u[7].x + bias8[7]);
        float4 hi0 = make_float4(u[0].y + bias8[0], u[1].y + bias8[1],
                                 u[2].y + bias8[2], u[3].y + bias8[3]);
        float4 hi1 = make_float4(u[4].y + bias8[4], u[5].y + bias8[5],
                                 u[6].y + bias8[6], u[7].y + bias8[7]);
        *(float4*)&C[(size_t)row_lo * N + n0 + tcg * 8]           = lo0;
        *(float4*)&C[(size_t)row_lo * N + n0 + tcg * 8 + 4]       = lo1;
        *(float4*)&C[(size_t)(row_lo + 1) * N + n0 + tcg * 8]     = hi0;
        *(float4*)&C[(size_t)(row_lo + 1) * N + n0 + tcg * 8 + 4] = hi1;
    }
}

// ---------------------------------------------------------------------------
// Banded quadratic attention with f32x2 + duplicated-pair smem:
//   out_t = sum_{s<=t, t-s<window} gamma^(t-s) (q_t . k_s)^2 v_s
// ---------------------------------------------------------------------------
#define ATTN_SMEM (8192 + 16384 + 16384 + 16384)   // Qs + Ks2 + Vs2 + Ws = 56 KB

__global__ __launch_bounds__(128) void attn_kernel()
{
    extern __shared__ __align__(16) char smem[];
    float (*Qs)[64]  = (float (*)[64])(smem);                 // [32][64] floats
    u64   (*Ks2)[64] = (u64   (*)[64])(smem + 8192);          // [32][64] dup pairs
    u64   (*Vs2)[32] = (u64   (*)[32])(smem + 8192 + 16384);  // [64][32] dup pairs
    float (*Ws)[64]  = (float (*)[64])(smem + 8192 + 32768);  // [64][64]

    const int tid = threadIdx.x;
    const int bh = blockIdx.y;
    const int b  = bh >> 4;
    const int h  = bh & 15;
    const int t0 = blockIdx.x * 64;

    const int r = tid >> 1;
    const int c = (tid & 1) * 16;

    // load Q tile transposed (once per block)
    {
        const float* qp = &g_q[(size_t)(b * SEQ + t0 + r) * HID + h * HD + c];
        #pragma unroll
        for (int v = 0; v < 4; v++) {
            float4 q4 = *(const float4*)(qp + v * 4);
            Qs[c + v*4 + 0][r] = q4.x; Qs[c + v*4 + 1][r] = q4.y;
            Qs[c + v*4 + 2][r] = q4.z; Qs[c + v*4 + 3][r] = q4.w;
        }
    }

    const int tq  = tid >> 4;    // phase-1 q group (8 queries = 4 pairs)
    const int ts  = tid & 15;    // phase-1 s group (4)
    const int tq2 = tid & 15;    // phase-2 q group (4 queries = 2 pairs)
    const int td  = tid >> 4;    // phase-2 d group (4 dims)

    float gqv[8], ginv[4];
    #pragma unroll
    for (int u = 0; u < 8; u++) gqv[u] = exp2f((float)(tq * 8 + u) * LOG2G);
    #pragma unroll
    for (int j = 0; j < 4; j++) ginv[j] = exp2f((float)(-(ts * 4 + j)) * LOG2G);

    u64 op[2][4];
    #pragma unroll
    for (int i = 0; i < 2; i++)
        #pragma unroll
        for (int j = 0; j < 4; j++) op[i][j] = 0ull;

    const int lo  = t0 - WIN + 1;
    const int st0 = (lo > 0 ? lo : 0) >> 6;
    const int st1 = t0 >> 6;

    for (int st = st0; st <= st1; st++) {
        const int sbase = st * 64;
        {
            const float* kp = &g_k[(size_t)(b * SEQ + sbase + r) * HID + h * HD + c];
            #pragma unroll
            for (int v = 0; v < 4; v++) {
                float4 k4 = *(const float4*)(kp + v * 4);
                Ks2[c + v*4 + 0][r] = pack2(k4.x, k4.x);
                Ks2[c + v*4 + 1][r] = pack2(k4.y, k4.y);
                Ks2[c + v*4 + 2][r] = pack2(k4.z, k4.z);
                Ks2[c + v*4 + 3][r] = pack2(k4.w, k4.w);
            }
            const float* vp = &g_v[(size_t)(b * SEQ + sbase + r) * HID + h * HD + c];
            #pragma unroll
            for (int v = 0; v < 4; v++) {
                float4 v4 = *(const float4*)(vp + v * 4);
                *(ulonglong2*)&Vs2[r][c + v*4]     = make_ulonglong2(pack2(v4.x,v4.x), pack2(v4.y,v4.y));
                *(ulonglong2*)&Vs2[r][c + v*4 + 2] = make_ulonglong2(pack2(v4.z,v4.z), pack2(v4.w,v4.w));
            }
        }
        __syncthreads();

        // phase 1: scores, 4 q-pairs x 4 s per thread
        u64 sp[4][4];
        #pragma unroll
        for (int i = 0; i < 4; i++)
            #pragma unroll
            for (int j = 0; j < 4; j++) sp[i][j] = 0ull;

        #pragma unroll
        for (int d = 0; d < 32; d++) {
            ulonglong2 ql = *(const ulonglong2*)&Qs[d][tq * 8];
            ulonglong2 qh = *(const ulonglong2*)&Qs[d][tq * 8 + 4];
            ulonglong2 k2 = *(const ulonglong2*)&Ks2[d][ts * 4];
            ulonglong2 k3 = *(const ulonglong2*)&Ks2[d][ts * 4 + 2];
            u64 qp2[4] = {ql.x, ql.y, qh.x, qh.y};
            u64 kp2[4] = {k2.x, k2.y, k3.x, k3.y};
            #pragma unroll
            for (int i = 0; i < 4; i++)
                #pragma unroll
                for (int j = 0; j < 4; j++)
                    sp[i][j] = ffma2(qp2[i], kp2[j], sp[i][j]);
        }

        // weight + transposed store: w = s^2 * gamma^(q + (t0-sbase) - s)
        {
            const float gt = exp2f((float)(t0 - sbase) * LOG2G);
            float cq[8];
            #pragma unroll
            for (int u = 0; u < 8; u++) cq[u] = gqv[u] * gt;
            const bool diag = (st == st1);

            #pragma unroll
            for (int i = 0; i < 4; i++) {
                const int q_lo = tq * 8 + 2 * i;
                #pragma unroll
                for (int j = 0; j < 4; j++) {
                    const int sl = ts * 4 + j;
                    float2 sv = unpack2(sp[i][j]);
                    float w0 = sv.x * sv.x * cq[2*i]   * ginv[j];
                    float w1 = sv.y * sv.y * cq[2*i+1] * ginv[j];
                    if (diag) {
                        if (sl > q_lo)     w0 = 0.f;
                        if (sl > q_lo + 1) w1 = 0.f;
                    }
                    *(u64*)&Ws[sl][q_lo] = pack2(w0, w1);
                }
            }
        }
        __syncthreads();

        // phase 2: O += Ws^T V, 2 q-pairs x 4 dims per thread
        #pragma unroll 8
        for (int s2 = 0; s2 < 64; s2++) {
            ulonglong2 wp = *(const ulonglong2*)&Ws[s2][tq2 * 4];
            ulonglong2 v0 = *(const ulonglong2*)&Vs2[s2][td * 4];
            ulonglong2 v1 = *(const ulonglong2*)&Vs2[s2][td * 4 + 2];
            u64 wpp[2] = {wp.x, wp.y};
            u64 vp2[4] = {v0.x, v0.y, v1.x, v1.y};
            #pragma unroll
            for (int i = 0; i < 2; i++)
                #pragma unroll
                for (int j = 0; j < 4; j++)
                    op[i][j] = ffma2(wpp[i], vp2[j], op[i][j]);
        }
        __syncthreads();
    }

    #pragma unroll
    for (int i = 0; i < 2; i++) {
        float2 u[4];
        #pragma unroll
        for (int j = 0; j < 4; j++) u[j] = unpack2(op[i][j]);
        const int t_lo = t0 + tq2 * 4 + 2 * i;
        float4 olo = make_float4(u[0].x, u[1].x, u[2].x, u[3].x);
        float4 ohi = make_float4(u[0].y, u[1].y, u[2].y, u[3].y);
        *(float4*)&g_att[(size_t)(b * SEQ + t_lo) * HID + h * HD + td * 4]     = olo;
        *(float4*)&g_att[(size_t)(b * SEQ + t_lo + 1) * HID + h * HD + td * 4] = ohi;
    }
}

// ---------------------------------------------------------------------------
extern "C" void kernel_launch(void* const* d_in, const int* in_sizes, int n_in,
                              void* d_out, int out_size)
{
    const float* x  = (const float*)d_in[0];
    const float* qw = (const float*)d_in[1];
    const float* qb = (const float*)d_in[2];
    const float* kw = (const float*)d_in[3];
    const float* kb = (const float*)d_in[4];
    const float* vw = (const float*)d_in[5];
    const float* vb = (const float*)d_in[6];
    const float* ow = (const float*)d_in[7];
    const float* ob = (const float*)d_in[8];
    float* out = (float*)d_out;

    float *pq, *pk, *pv, *pa;
    cudaGetSymbolAddress((void**)&pq, g_q);
    cudaGetSymbolAddress((void**)&pk, g_k);
    cudaGetSymbolAddress((void**)&pv, g_v);
    cudaGetSymbolAddress((void**)&pa, g_att);

    cudaFuncSetAttribute(attn_kernel,
                         cudaFuncAttributeMaxDynamicSharedMemorySize, ATTN_SMEM);

    // fused QKV projections: 128x128 tiles, grid (4,16,3) = 192 blocks
    gemm_qkv_kernel<<<dim3(4, 16, 3), 256>>>(x, qw, qb, pq, kw, kb, pk, vw, vb, pv);
    // banded quadratic attention
    attn_kernel<<<dim3(SEQ / 64, BATCH * NH), 128, ATTN_SMEM>>>();
    // output projection: 128x64 tiles, grid (8,16) = 128 blocks
    gemm_o_kernel<<<dim3(8, 16), 256>>>(pa, ow, ob, out);
}

// round 16
// speedup vs baseline: 1.0009x; 1.0009x over previous
#include <cuda_runtime.h>

#define HID   512
#define NH    16
#define HD    32
#define SEQ   1024
#define BATCH 2
#define MROWS (BATCH*SEQ)   // 2048
#define WIN   128           // gamma^128/(1-gamma) ~ 1.4e-5: safe truncation

// scratch (no allocations allowed)
__device__ float g_q[MROWS*HID];
__device__ float g_k[MROWS*HID];
__device__ float g_v[MROWS*HID];
__device__ float g_att[MROWS*HID];

typedef unsigned long long u64;

#define LOG2G (-0.15200309344504995f)   // log2(0.9)

// ---- packed f32x2 helpers (SASS FFMA2 — only reachable via PTX) ----------
__device__ __forceinline__ u64 pack2(float lo, float hi) {
    u64 r; asm("mov.b64 %0,{%1,%2};" : "=l"(r) : "f"(lo), "f"(hi)); return r;
}
__device__ __forceinline__ float2 unpack2(u64 v) {
    float2 r; asm("mov.b64 {%0,%1},%2;" : "=f"(r.x), "=f"(r.y) : "l"(v)); return r;
}
__device__ __forceinline__ u64 ffma2(u64 a, u64 b, u64 c) {
    u64 d; asm("fma.rn.f32x2 %0,%1,%2,%3;" : "=l"(d) : "l"(a), "l"(b), "l"(c)); return d;
}

// ---------------------------------------------------------------------------
// Fused QKV GEMM: C[M,N] = A @ W + bias, M=2048, N=K=512.
// 128x128 block tile, BK=16, 256 threads, 8x8 scalar microtile = 4 f32x2
// pairs (M) x 8 cols (N). B pre-duplicated as {b,b} u64 pairs in smem.
// 8 wavefronts per warp-kk for 32 FFMA2 (0.25 wf/FFMA2).
// __launch_bounds__(256, 2): cap regs at 128 so 2 blocks co-reside per SM
// (R13 at 134 regs fell to 1 block/SM and went latency-bound).
// ---------------------------------------------------------------------------
__global__ __launch_bounds__(256, 2) void gemm_qkv_kernel(
    const float* __restrict__ A,
    const float* __restrict__ W0, const float* __restrict__ B0, float* __restrict__ C0,
    const float* __restrict__ W1, const float* __restrict__ B1, float* __restrict__ C1,
    const float* __restrict__ W2, const float* __restrict__ B2, float* __restrict__ C2)
{
    const int K = 512, N = 512;
    const float* W = W0; const float* bias = B0; float* C = C0;
    if (blockIdx.z == 1) { W = W1; bias = B1; C = C1; }
    else if (blockIdx.z == 2) { W = W2; bias = B2; C = C2; }

    __shared__ __align__(16) float As[2][16][128];   // 16 KB
    __shared__ __align__(16) u64   Bs[2][16][128];   // 32 KB (duplicated pairs)

    const int tid = threadIdx.x;
    const int m0 = blockIdx.y * 128;
    const int n0 = blockIdx.x * 128;
    const int tr  = tid & 15;        // m-group: 8 rows = 4 pairs
    const int tcg = tid >> 4;        // n-group: 8 cols

    // A load: row = tid>>1 (0..127), k-offset = (tid&1)*8 : 2 float4
    const int ar = tid >> 1;
    const int ak = (tid & 1) * 8;
    // B load: bk = tid>>4 (0..15), bn = (tid&15)*8 : 2 float4
    const int bk = tid >> 4;
    const int bn = (tid & 15) * 8;

    u64 acc[4][8];
    #pragma unroll
    for (int i = 0; i < 4; i++)
        #pragma unroll
        for (int j = 0; j < 8; j++) acc[i][j] = 0ull;

    float4 a0, a1, b0, b1;
    {   // prologue: tile 0
        const float* ap = &A[(size_t)(m0 + ar) * K + ak];
        a0 = *(const float4*)(ap + 0);
        a1 = *(const float4*)(ap + 4);
        b0 = *(const float4*)&W[(size_t)bk * N + n0 + bn];
        b1 = *(const float4*)&W[(size_t)bk * N + n0 + bn + 4];
        As[0][ak+0][ar] = a0.x; As[0][ak+1][ar] = a0.y;
        As[0][ak+2][ar] = a0.z; As[0][ak+3][ar] = a0.w;
        As[0][ak+4][ar] = a1.x; As[0][ak+5][ar] = a1.y;
        As[0][ak+6][ar] = a1.z; As[0][ak+7][ar] = a1.w;
        *(ulonglong2*)&Bs[0][bk][bn]     = make_ulonglong2(pack2(b0.x,b0.x), pack2(b0.y,b0.y));
        *(ulonglong2*)&Bs[0][bk][bn + 2] = make_ulonglong2(pack2(b0.z,b0.z), pack2(b0.w,b0.w));
        *(ulonglong2*)&Bs[0][bk][bn + 4] = make_ulonglong2(pack2(b1.x,b1.x), pack2(b1.y,b1.y));
        *(ulonglong2*)&Bs[0][bk][bn + 6] = make_ulonglong2(pack2(b1.z,b1.z), pack2(b1.w,b1.w));
    }
    __syncthreads();

    for (int k0 = 0; k0 < K; k0 += 16) {
        const int buf = (k0 >> 4) & 1;
        const int nxt = buf ^ 1;
        const bool more = (k0 + 16 < K);
        if (more) {
            const int kn = k0 + 16;
            const float* ap = &A[(size_t)(m0 + ar) * K + kn + ak];
            a0 = *(const float4*)(ap + 0);
            a1 = *(const float4*)(ap + 4);
            b0 = *(const float4*)&W[(size_t)(kn + bk) * N + n0 + bn];
            b1 = *(const float4*)&W[(size_t)(kn + bk) * N + n0 + bn + 4];
        }

        #pragma unroll
        for (int kk = 0; kk < 16; kk++) {
            ulonglong2 al  = *(const ulonglong2*)&As[buf][kk][tr * 8];
            ulonglong2 ah  = *(const ulonglong2*)&As[buf][kk][tr * 8 + 4];
            ulonglong2 b01 = *(const ulonglong2*)&Bs[buf][kk][tcg * 8];
            ulonglong2 b23 = *(const ulonglong2*)&Bs[buf][kk][tcg * 8 + 2];
            ulonglong2 b45 = *(const ulonglong2*)&Bs[buf][kk][tcg * 8 + 4];
            ulonglong2 b67 = *(const ulonglong2*)&Bs[buf][kk][tcg * 8 + 6];
            u64 ap2[4] = {al.x, al.y, ah.x, ah.y};
            u64 bp[8]  = {b01.x, b01.y, b23.x, b23.y, b45.x, b45.y, b67.x, b67.y};
            #pragma unroll
            for (int i = 0; i < 4; i++)
                #pragma unroll
                for (int j = 0; j < 8; j++)
                    acc[i][j] = ffma2(ap2[i], bp[j], acc[i][j]);
        }

        if (more) {
            As[nxt][ak+0][ar] = a0.x; As[nxt][ak+1][ar] = a0.y;
            As[nxt][ak+2][ar] = a0.z; As[nxt][ak+3][ar] = a0.w;
            As[nxt][ak+4][ar] = a1.x; As[nxt][ak+5][ar] = a1.y;
            As[nxt][ak+6][ar] = a1.z; As[nxt][ak+7][ar] = a1.w;
            *(ulonglong2*)&Bs[nxt][bk][bn]     = make_ulonglong2(pack2(b0.x,b0.x), pack2(b0.y,b0.y));
            *(ulonglong2*)&Bs[nxt][bk][bn + 2] = make_ulonglong2(pack2(b0.z,b0.z), pack2(b0.w,b0.w));
            *(ulonglong2*)&Bs[nxt][bk][bn + 4] = make_ulonglong2(pack2(b1.x,b1.x), pack2(b1.y,b1.y));
            *(ulonglong2*)&Bs[nxt][bk][bn + 6] = make_ulonglong2(pack2(b1.z,b1.z), pack2(b1.w,b1.w));
        }
        __syncthreads();
    }

    // epilogue
    float bias8[8];
    #pragma unroll
    for (int j = 0; j < 8; j++) bias8[j] = bias[n0 + tcg * 8 + j];

    #pragma unroll
    for (int p = 0; p < 4; p++) {
        float2 u[8];
        #pragma unroll
        for (int j = 0; j < 8; j++) u[j] = unpack2(acc[p][j]);
        const int row_lo = m0 + tr * 8 + 2 * p;
        float4 lo0 = make_float4(u[0].x + bias8[0], u[1].x + bias8[1],
                                 u[2].x + bias8[2], u[3].x + bias8[3]);
        float4 lo1 = make_float4(u[4].x + bias8[4], u[5].x + bias8[5],
                                 u[6].x + bias8[6], u[7].x + bias8[7]);
        float4 hi0 = make_float4(u[0].y + bias8[0], u[1].y + bias8[1],
                                 u[2].y + bias8[2], u[3].y + bias8[3]);
        float4 hi1 = make_float4(u[4].y + bias8[4], u[5].y + bias8[5],
                                 u[6].y + bias8[6], u[7].y + bias8[7]);
        *(float4*)&C[(size_t)row_lo * N + n0 + tcg * 8]           = lo0;
        *(float4*)&C[(size_t)row_lo * N + n0 + tcg * 8 + 4]       = lo1;
        *(float4*)&C[(size_t)(row_lo + 1) * N + n0 + tcg * 8]     = hi0;
        *(float4*)&C[(size_t)(row_lo + 1) * N + n0 + tcg * 8 + 4] = hi1;
    }
}

// ---------------------------------------------------------------------------
// O-projection GEMM: 128x64 block tile, 256 threads, 2-pair x 8 microtile.
// (128 blocks -> good chip fill for the single trailing GEMM.)
// ---------------------------------------------------------------------------
__global__ __launch_bounds__(256) void gemm_o_kernel(
    const float* __restrict__ A,
    const float* __restrict__ W, const float* __restrict__ bias,
    float* __restrict__ C)
{
    const int K = 512, N = 512;
    __shared__ __align__(16) float As[2][16][128];   // 16 KB
    __shared__ __align__(16) u64   Bs[2][16][64];    // 16 KB (duplicated pairs)

    const int tid = threadIdx.x;
    const int m0 = blockIdx.y * 128;
    const int n0 = blockIdx.x * 64;
    const int tr  = tid & 31;        // m-group: 4 rows = 2 pairs
    const int tcg = tid >> 5;        // n-group: 8 cols (constant per warp)

    const int ar = tid >> 1;
    const int ak = (tid & 1) * 8;
    const int bk = tid >> 4;
    const int bn = (tid & 15) * 4;

    u64 acc[2][8];
    #pragma unroll
    for (int i = 0; i < 2; i++)
        #pragma unroll
        for (int j = 0; j < 8; j++) acc[i][j] = 0ull;

    float4 a0, a1, b0;
    {
        const float* ap = &A[(size_t)(m0 + ar) * K + ak];
        a0 = *(const float4*)(ap + 0);
        a1 = *(const float4*)(ap + 4);
        b0 = *(const float4*)&W[(size_t)bk * N + n0 + bn];
        As[0][ak+0][ar] = a0.x; As[0][ak+1][ar] = a0.y;
        As[0][ak+2][ar] = a0.z; As[0][ak+3][ar] = a0.w;
        As[0][ak+4][ar] = a1.x; As[0][ak+5][ar] = a1.y;
        As[0][ak+6][ar] = a1.z; As[0][ak+7][ar] = a1.w;
        *(ulonglong2*)&Bs[0][bk][bn]     = make_ulonglong2(pack2(b0.x,b0.x), pack2(b0.y,b0.y));
        *(ulonglong2*)&Bs[0][bk][bn + 2] = make_ulonglong2(pack2(b0.z,b0.z), pack2(b0.w,b0.w));
    }
    __syncthreads();

    for (int k0 = 0; k0 < K; k0 += 16) {
        const int buf = (k0 >> 4) & 1;
        const int nxt = buf ^ 1;
        const bool more = (k0 + 16 < K);
        if (more) {
            const int kn = k0 + 16;
            const float* ap = &A[(size_t)(m0 + ar) * K + kn + ak];
            a0 = *(const float4*)(ap + 0);
            a1 = *(const float4*)(ap + 4);
            b0 = *(const float4*)&W[(size_t)(kn + bk) * N + n0 + bn];
        }

        #pragma unroll
        for (int kk = 0; kk < 16; kk++) {
            ulonglong2 a2  = *(const ulonglong2*)&As[buf][kk][tr * 4];
            ulonglong2 b01 = *(const ulonglong2*)&Bs[buf][kk][tcg * 8];
            ulonglong2 b23 = *(const ulonglong2*)&Bs[buf][kk][tcg * 8 + 2];
            ulonglong2 b45 = *(const ulonglong2*)&Bs[buf][kk][tcg * 8 + 4];
            ulonglong2 b67 = *(const ulonglong2*)&Bs[buf][kk][tcg * 8 + 6];
            u64 ap2[2] = {a2.x, a2.y};
            u64 bp[8]  = {b01.x, b01.y, b23.x, b23.y, b45.x, b45.y, b67.x, b67.y};
            #pragma unroll
            for (int i = 0; i < 2; i++)
                #pragma unroll
                for (int j = 0; j < 8; j++)
                    acc[i][j] = ffma2(ap2[i], bp[j], acc[i][j]);
        }

        if (more) {
            As[nxt][ak+0][ar] = a0.x; As[nxt][ak+1][ar] = a0.y;
            As[nxt][ak+2][ar] = a0.z; As[nxt][ak+3][ar] = a0.w;
            As[nxt][ak+4][ar] = a1.x; As[nxt][ak+5][ar] = a1.y;
            As[nxt][ak+6][ar] = a1.z; As[nxt][ak+7][ar] = a1.w;
            *(ulonglong2*)&Bs[nxt][bk][bn]     = make_ulonglong2(pack2(b0.x,b0.x), pack2(b0.y,b0.y));
            *(ulonglong2*)&Bs[nxt][bk][bn + 2] = make_ulonglong2(pack2(b0.z,b0.z), pack2(b0.w,b0.w));
        }
        __syncthreads();
    }

    float bias8[8];
    #pragma unroll
    for (int j = 0; j < 8; j++) bias8[j] = bias[n0 + tcg * 8 + j];

    #pragma unroll
    for (int p = 0; p < 2; p++) {
        float2 u[8];
        #pragma unroll
        for (int j = 0; j < 8; j++) u[j] = unpack2(acc[p][j]);
        const int row_lo = m0 + tr * 4 + 2 * p;
        float4 lo0 = make_float4(u[0].x + bias8[0], u[1].x + bias8[1],
                                 u[2].x + bias8[2], u[3].x + bias8[3]);
        float4 lo1 = make_float4(u[4].x + bias8[4], u[5].x + bias8[5],
                                 u[6].x + bias8[6], u[7].x + bias8[7]);
        float4 hi0 = make_float4(u[0].y + bias8[0], u[1].y + bias8[1],
                                 u[2].y + bias8[2], u[3].y + bias8[3]);
        float4 hi1 = make_float4(u[4].y + bias8[4], u[5].y + bias8[5],
                                 u[6].y + bias8[6], u[7].y + bias8[7]);
        *(float4*)&C[(size_t)row_lo * N + n0 + tcg * 8]           = lo0;
        *(float4*)&C[(size_t)row_lo * N + n0 + tcg * 8 + 4]       = lo1;
        *(float4*)&C[(size_t)(row_lo + 1) * N + n0 + tcg * 8]     = hi0;
        *(float4*)&C[(size_t)(row_lo + 1) * N + n0 + tcg * 8 + 4] = hi1;
    }
}

// ---------------------------------------------------------------------------
// Banded quadratic attention with f32x2 + duplicated-pair smem:
//   out_t = sum_{s<=t, t-s<window} gamma^(t-s) (q_t . k_s)^2 v_s
// ---------------------------------------------------------------------------
#define ATTN_SMEM (8192 + 16384 + 16384 + 16384)   // Qs + Ks2 + Vs2 + Ws = 56 KB

__global__ __launch_bounds__(128) void attn_kernel()
{
    extern __shared__ __align__(16) char smem[];
    float (*Qs)[64]  = (float (*)[64])(smem);                 // [32][64] floats
    u64   (*Ks2)[64] = (u64   (*)[64])(smem + 8192);          // [32][64] dup pairs
    u64   (*Vs2)[32] = (u64   (*)[32])(smem + 8192 + 16384);  // [64][32] dup pairs
    float (*Ws)[64]  = (float (*)[64])(smem + 8192 + 32768);  // [64][64]

    const int tid = threadIdx.x;
    const int bh = blockIdx.y;
    const int b  = bh >> 4;
    const int h  = bh & 15;
    const int t0 = blockIdx.x * 64;

    const int r = tid >> 1;
    const int c = (tid & 1) * 16;

    // load Q tile transposed (once per block)
    {
        const float* qp = &g_q[(size_t)(b * SEQ + t0 + r) * HID + h * HD + c];
        #pragma unroll
        for (int v = 0; v < 4; v++) {
            float4 q4 = *(const float4*)(qp + v * 4);
            Qs[c + v*4 + 0][r] = q4.x; Qs[c + v*4 + 1][r] = q4.y;
            Qs[c + v*4 + 2][r] = q4.z; Qs[c + v*4 + 3][r] = q4.w;
        }
    }

    const int tq  = tid >> 4;    // phase-1 q group (8 queries = 4 pairs)
    const int ts  = tid & 15;    // phase-1 s group (4)
    const int tq2 = tid & 15;    // phase-2 q group (4 queries = 2 pairs)
    const int td  = tid >> 4;    // phase-2 d group (4 dims)

    float gqv[8], ginv[4];
    #pragma unroll
    for (int u = 0; u < 8; u++) gqv[u] = exp2f((float)(tq * 8 + u) * LOG2G);
    #pragma unroll
    for (int j = 0; j < 4; j++) ginv[j] = exp2f((float)(-(ts * 4 + j)) * LOG2G);

    u64 op[2][4];
    #pragma unroll
    for (int i = 0; i < 2; i++)
        #pragma unroll
        for (int j = 0; j < 4; j++) op[i][j] = 0ull;

    const int lo  = t0 - WIN + 1;
    const int st0 = (lo > 0 ? lo : 0) >> 6;
    const int st1 = t0 >> 6;

    for (int st = st0; st <= st1; st++) {
        const int sbase = st * 64;
        {
            const float* kp = &g_k[(size_t)(b * SEQ + sbase + r) * HID + h * HD + c];
            #pragma unroll
            for (int v = 0; v < 4; v++) {
                float4 k4 = *(const float4*)(kp + v * 4);
                Ks2[c + v*4 + 0][r] = pack2(k4.x, k4.x);
                Ks2[c + v*4 + 1][r] = pack2(k4.y, k4.y);
                Ks2[c + v*4 + 2][r] = pack2(k4.z, k4.z);
                Ks2[c + v*4 + 3][r] = pack2(k4.w, k4.w);
            }
            const float* vp = &g_v[(size_t)(b * SEQ + sbase + r) * HID + h * HD + c];
            #pragma unroll
            for (int v = 0; v < 4; v++) {
                float4 v4 = *(const float4*)(vp + v * 4);
                *(ulonglong2*)&Vs2[r][c + v*4]     = make_ulonglong2(pack2(v4.x,v4.x), pack2(v4.y,v4.y));
                *(ulonglong2*)&Vs2[r][c + v*4 + 2] = make_ulonglong2(pack2(v4.z,v4.z), pack2(v4.w,v4.w));
            }
        }
        __syncthreads();

        // phase 1: scores, 4 q-pairs x 4 s per thread
        u64 sp[4][4];
        #pragma unroll
        for (int i = 0; i < 4; i++)
            #pragma unroll
            for (int j = 0; j < 4; j++) sp[i][j] = 0ull;

        #pragma unroll
        for (int d = 0; d < 32; d++) {
            ulonglong2 ql = *(const ulonglong2*)&Qs[d][tq * 8];
            ulonglong2 qh = *(const ulonglong2*)&Qs[d][tq * 8 + 4];
            ulonglong2 k2 = *(const ulonglong2*)&Ks2[d][ts * 4];
            ulonglong2 k3 = *(const ulonglong2*)&Ks2[d][ts * 4 + 2];
            u64 qp2[4] = {ql.x, ql.y, qh.x, qh.y};
            u64 kp2[4] = {k2.x, k2.y, k3.x, k3.y};
            #pragma unroll
            for (int i = 0; i < 4; i++)
                #pragma unroll
                for (int j = 0; j < 4; j++)
                    sp[i][j] = ffma2(qp2[i], kp2[j], sp[i][j]);
        }

        // weight + transposed store: w = s^2 * gamma^(q + (t0-sbase) - s)
        {
            const float gt = exp2f((float)(t0 - sbase) * LOG2G);
            float cq[8];
            #pragma unroll
            for (int u = 0; u < 8; u++) cq[u] = gqv[u] * gt;
            const bool diag = (st == st1);

            #pragma unroll
            for (int i = 0; i < 4; i++) {
                const int q_lo = tq * 8 + 2 * i;
                #pragma unroll
                for (int j = 0; j < 4; j++) {
                    const int sl = ts * 4 + j;
                    float2 sv = unpack2(sp[i][j]);
                    float w0 = sv.x * sv.x * cq[2*i]   * ginv[j];
                    float w1 = sv.y * sv.y * cq[2*i+1] * ginv[j];
                    if (diag) {
                        if (sl > q_lo)     w0 = 0.f;
                        if (sl > q_lo + 1) w1 = 0.f;
                    }
                    *(u64*)&Ws[sl][q_lo] = pack2(w0, w1);
                }
            }
        }
        __syncthreads();

        // phase 2: O += Ws^T V, 2 q-pairs x 4 dims per thread
        #pragma unroll 8
        for (int s2 = 0; s2 < 64; s2++) {
            ulonglong2 wp = *(const ulonglong2*)&Ws[s2][tq2 * 4];
            ulonglong2 v0 = *(const ulonglong2*)&Vs2[s2][td * 4];
            ulonglong2 v1 = *(const ulonglong2*)&Vs2[s2][td * 4 + 2];
            u64 wpp[2] = {wp.x, wp.y};
            u64 vp2[4] = {v0.x, v0.y, v1.x, v1.y};
            #pragma unroll
            for (int i = 0; i < 2; i++)
                #pragma unroll
                for (int j = 0; j < 4; j++)
                    op[i][j] = ffma2(wpp[i], vp2[j], op[i][j]);
        }
        __syncthreads();
    }

    #pragma unroll
    for (int i = 0; i < 2; i++) {
        float2 u[4];
        #pragma unroll
        for (int j = 0; j < 4; j++) u[j] = unpack2(op[i][j]);
        const int t_lo = t0 + tq2 * 4 + 2 * i;
        float4 olo = make_float4(u[0].x, u[1].x, u[2].x, u[3].x);
        float4 ohi = make_float4(u[0].y, u[1].y, u[2].y, u[3].y);
        *(float4*)&g_att[(size_t)(b * SEQ + t_lo) * HID + h * HD + td * 4]     = olo;
        *(float4*)&g_att[(size_t)(b * SEQ + t_lo + 1) * HID + h * HD + td * 4] = ohi;
    }
}

// ---------------------------------------------------------------------------
extern "C" void kernel_launch(void* const* d_in, const int* in_sizes, int n_in,
                              void* d_out, int out_size)
{
    const float* x  = (const float*)d_in[0];
    const float* qw = (const float*)d_in[1];
    const float* qb = (const float*)d_in[2];
    const float* kw = (const float*)d_in[3];
    const float* kb = (const float*)d_in[4];
    const float* vw = (const float*)d_in[5];
    const float* vb = (const float*)d_in[6];
    const float* ow = (const float*)d_in[7];
    const float* ob = (const float*)d_in[8];
    float* out = (float*)d_out;

    float *pq, *pk, *pv, *pa;
    cudaGetSymbolAddress((void**)&pq, g_q);
    cudaGetSymbolAddress((void**)&pk, g_k);
    cudaGetSymbolAddress((void**)&pv, g_v);
    cudaGetSymbolAddress((void**)&pa, g_att);

    cudaFuncSetAttribute(attn_kernel,
                         cudaFuncAttributeMaxDynamicSharedMemorySize, ATTN_SMEM);

    // fused QKV projections: 128x128 tiles, grid (4,16,3) = 192 blocks
    gemm_qkv_kernel<<<dim3(4, 16, 3), 256>>>(x, qw, qb, pq, kw, kb, pk, vw, vb, pv);
    // banded quadratic attention
    attn_kernel<<<dim3(SEQ / 64, BATCH * NH), 128, ATTN_SMEM>>>();
    // output projection: 128x64 tiles, grid (8,16) = 128 blocks
    gemm_o_kernel<<<dim3(8, 16), 256>>>(pa, ow, ob, out);
}

// round 17
// speedup vs baseline: 1.0669x; 1.0660x over previous
#include <cuda_runtime.h>

#define HID   512
#define NH    16
#define HD    32
#define SEQ   1024
#define BATCH 2
#define MROWS (BATCH*SEQ)   // 2048
#define WIN   128           // gamma^128/(1-gamma) ~ 1.4e-5: safe truncation

// scratch (no allocations allowed)
__device__ float g_q[MROWS*HID];
__device__ float g_k[MROWS*HID];
__device__ float g_v[MROWS*HID];
__device__ float g_att[MROWS*HID];

typedef unsigned long long u64;

#define LOG2G (-0.15200309344504995f)   // log2(0.9)

// ---- packed f32x2 helpers (SASS FFMA2 — only reachable via PTX) ----------
__device__ __forceinline__ u64 pack2(float lo, float hi) {
    u64 r; asm("mov.b64 %0,{%1,%2};" : "=l"(r) : "f"(lo), "f"(hi)); return r;
}
__device__ __forceinline__ float2 unpack2(u64 v) {
    float2 r; asm("mov.b64 {%0,%1},%2;" : "=f"(r.x), "=f"(r.y) : "l"(v)); return r;
}
__device__ __forceinline__ u64 ffma2(u64 a, u64 b, u64 c) {
    u64 d; asm("fma.rn.f32x2 %0,%1,%2,%3;" : "=l"(d) : "l"(a), "l"(b), "l"(c)); return d;
}

// ---------------------------------------------------------------------------
// Fused QKV GEMM: C[M,N] = A @ W + bias, M=2048, N=K=512.
// 128x64 block tile, BK=16, 128 threads, 8x8 microtile = 4 f32x2 pairs (M)
// x 8 cols (N). Same 0.25 wf/FFMA2 economics as the 128x128 config but with
// 384 blocks (~2.6/SM, 3-4 co-resident) instead of 192 (0.65 waves).
// B pre-duplicated as {b,b} u64 pairs. smem = 32 KB static.
// ---------------------------------------------------------------------------
__global__ __launch_bounds__(128) void gemm_qkv_kernel(
    const float* __restrict__ A,
    const float* __restrict__ W0, const float* __restrict__ B0, float* __restrict__ C0,
    const float* __restrict__ W1, const float* __restrict__ B1, float* __restrict__ C1,
    const float* __restrict__ W2, const float* __restrict__ B2, float* __restrict__ C2)
{
    const int K = 512, N = 512;
    const float* W = W0; const float* bias = B0; float* C = C0;
    if (blockIdx.z == 1) { W = W1; bias = B1; C = C1; }
    else if (blockIdx.z == 2) { W = W2; bias = B2; C = C2; }

    __shared__ __align__(16) float As[2][16][128];   // 16 KB
    __shared__ __align__(16) u64   Bs[2][16][64];    // 16 KB (duplicated pairs)

    const int tid = threadIdx.x;
    const int m0 = blockIdx.y * 128;
    const int n0 = blockIdx.x * 64;
    const int tr  = tid & 15;        // m-group: 8 rows = 4 pairs
    const int tcg = tid >> 4;        // n-group: 8 cols (0..7)

    // A load: thread owns one row (m0+tid), 16 k values (4 float4)
    // B load: bk = tid>>3 (0..15), bn = (tid&7)*8 : 2 float4
    const int bk = tid >> 3;
    const int bn = (tid & 7) * 8;

    u64 acc[4][8];
    #pragma unroll
    for (int i = 0; i < 4; i++)
        #pragma unroll
        for (int j = 0; j < 8; j++) acc[i][j] = 0ull;

    float4 a0, a1, a2, a3, b0, b1;
    {   // prologue: tile 0
        const float* ap = &A[(size_t)(m0 + tid) * K];
        a0 = *(const float4*)(ap + 0);
        a1 = *(const float4*)(ap + 4);
        a2 = *(const float4*)(ap + 8);
        a3 = *(const float4*)(ap + 12);
        b0 = *(const float4*)&W[(size_t)bk * N + n0 + bn];
        b1 = *(const float4*)&W[(size_t)bk * N + n0 + bn + 4];
        As[0][0][tid]  = a0.x; As[0][1][tid]  = a0.y; As[0][2][tid]  = a0.z; As[0][3][tid]  = a0.w;
        As[0][4][tid]  = a1.x; As[0][5][tid]  = a1.y; As[0][6][tid]  = a1.z; As[0][7][tid]  = a1.w;
        As[0][8][tid]  = a2.x; As[0][9][tid]  = a2.y; As[0][10][tid] = a2.z; As[0][11][tid] = a2.w;
        As[0][12][tid] = a3.x; As[0][13][tid] = a3.y; As[0][14][tid] = a3.z; As[0][15][tid] = a3.w;
        *(ulonglong2*)&Bs[0][bk][bn]     = make_ulonglong2(pack2(b0.x,b0.x), pack2(b0.y,b0.y));
        *(ulonglong2*)&Bs[0][bk][bn + 2] = make_ulonglong2(pack2(b0.z,b0.z), pack2(b0.w,b0.w));
        *(ulonglong2*)&Bs[0][bk][bn + 4] = make_ulonglong2(pack2(b1.x,b1.x), pack2(b1.y,b1.y));
        *(ulonglong2*)&Bs[0][bk][bn + 6] = make_ulonglong2(pack2(b1.z,b1.z), pack2(b1.w,b1.w));
    }
    __syncthreads();

    for (int k0 = 0; k0 < K; k0 += 16) {
        const int buf = (k0 >> 4) & 1;
        const int nxt = buf ^ 1;
        const bool more = (k0 + 16 < K);
        if (more) {
            const int kn = k0 + 16;
            const float* ap = &A[(size_t)(m0 + tid) * K + kn];
            a0 = *(const float4*)(ap + 0);
            a1 = *(const float4*)(ap + 4);
            a2 = *(const float4*)(ap + 8);
            a3 = *(const float4*)(ap + 12);
            b0 = *(const float4*)&W[(size_t)(kn + bk) * N + n0 + bn];
            b1 = *(const float4*)&W[(size_t)(kn + bk) * N + n0 + bn + 4];
        }

        #pragma unroll
        for (int kk = 0; kk < 16; kk++) {
            ulonglong2 al  = *(const ulonglong2*)&As[buf][kk][tr * 8];
            ulonglong2 ah  = *(const ulonglong2*)&As[buf][kk][tr * 8 + 4];
            ulonglong2 b01 = *(const ulonglong2*)&Bs[buf][kk][tcg * 8];
            ulonglong2 b23 = *(const ulonglong2*)&Bs[buf][kk][tcg * 8 + 2];
            ulonglong2 b45 = *(const ulonglong2*)&Bs[buf][kk][tcg * 8 + 4];
            ulonglong2 b67 = *(const ulonglong2*)&Bs[buf][kk][tcg * 8 + 6];
            u64 ap2[4] = {al.x, al.y, ah.x, ah.y};
            u64 bp[8]  = {b01.x, b01.y, b23.x, b23.y, b45.x, b45.y, b67.x, b67.y};
            #pragma unroll
            for (int i = 0; i < 4; i++)
                #pragma unroll
                for (int j = 0; j < 8; j++)
                    acc[i][j] = ffma2(ap2[i], bp[j], acc[i][j]);
        }

        if (more) {
            As[nxt][0][tid]  = a0.x; As[nxt][1][tid]  = a0.y; As[nxt][2][tid]  = a0.z; As[nxt][3][tid]  = a0.w;
            As[nxt][4][tid]  = a1.x; As[nxt][5][tid]  = a1.y; As[nxt][6][tid]  = a1.z; As[nxt][7][tid]  = a1.w;
            As[nxt][8][tid]  = a2.x; As[nxt][9][tid]  = a2.y; As[nxt][10][tid] = a2.z; As[nxt][11][tid] = a2.w;
            As[nxt][12][tid] = a3.x; As[nxt][13][tid] = a3.y; As[nxt][14][tid] = a3.z; As[nxt][15][tid] = a3.w;
            *(ulonglong2*)&Bs[nxt][bk][bn]     = make_ulonglong2(pack2(b0.x,b0.x), pack2(b0.y,b0.y));
            *(ulonglong2*)&Bs[nxt][bk][bn + 2] = make_ulonglong2(pack2(b0.z,b0.z), pack2(b0.w,b0.w));
            *(ulonglong2*)&Bs[nxt][bk][bn + 4] = make_ulonglong2(pack2(b1.x,b1.x), pack2(b1.y,b1.y));
            *(ulonglong2*)&Bs[nxt][bk][bn + 6] = make_ulonglong2(pack2(b1.z,b1.z), pack2(b1.w,b1.w));
        }
        __syncthreads();
    }

    // epilogue
    float bias8[8];
    #pragma unroll
    for (int j = 0; j < 8; j++) bias8[j] = bias[n0 + tcg * 8 + j];

    #pragma unroll
    for (int p = 0; p < 4; p++) {
        float2 u[8];
        #pragma unroll
        for (int j = 0; j < 8; j++) u[j] = unpack2(acc[p][j]);
        const int row_lo = m0 + tr * 8 + 2 * p;
        float4 lo0 = make_float4(u[0].x + bias8[0], u[1].x + bias8[1],
                                 u[2].x + bias8[2], u[3].x + bias8[3]);
        float4 lo1 = make_float4(u[4].x + bias8[4], u[5].x + bias8[5],
                                 u[6].x + bias8[6], u[7].x + bias8[7]);
        float4 hi0 = make_float4(u[0].y + bias8[0], u[1].y + bias8[1],
                                 u[2].y + bias8[2], u[3].y + bias8[3]);
        float4 hi1 = make_float4(u[4].y + bias8[4], u[5].y + bias8[5],
                                 u[6].y + bias8[6], u[7].y + bias8[7]);
        *(float4*)&C[(size_t)row_lo * N + n0 + tcg * 8]           = lo0;
        *(float4*)&C[(size_t)row_lo * N + n0 + tcg * 8 + 4]       = lo1;
        *(float4*)&C[(size_t)(row_lo + 1) * N + n0 + tcg * 8]     = hi0;
        *(float4*)&C[(size_t)(row_lo + 1) * N + n0 + tcg * 8 + 4] = hi1;
    }
}

// ---------------------------------------------------------------------------
// O-projection GEMM: 128x64 block tile, 256 threads, 2-pair x 8 microtile
// (proven R11 config, ~21 us, 128 blocks).
// ---------------------------------------------------------------------------
__global__ __launch_bounds__(256) void gemm_o_kernel(
    const float* __restrict__ A,
    const float* __restrict__ W, const float* __restrict__ bias,
    float* __restrict__ C)
{
    const int K = 512, N = 512;
    __shared__ __align__(16) float As[2][16][128];   // 16 KB
    __shared__ __align__(16) u64   Bs[2][16][64];    // 16 KB (duplicated pairs)

    const int tid = threadIdx.x;
    const int m0 = blockIdx.y * 128;
    const int n0 = blockIdx.x * 64;
    const int tr  = tid & 31;        // m-group: 4 rows = 2 pairs
    const int tcg = tid >> 5;        // n-group: 8 cols (constant per warp)

    const int ar = tid >> 1;
    const int ak = (tid & 1) * 8;
    const int bk = tid >> 4;
    const int bn = (tid & 15) * 4;

    u64 acc[2][8];
    #pragma unroll
    for (int i = 0; i < 2; i++)
        #pragma unroll
        for (int j = 0; j < 8; j++) acc[i][j] = 0ull;

    float4 a0, a1, b0;
    {
        const float* ap = &A[(size_t)(m0 + ar) * K + ak];
        a0 = *(const float4*)(ap + 0);
        a1 = *(const float4*)(ap + 4);
        b0 = *(const float4*)&W[(size_t)bk * N + n0 + bn];
        As[0][ak+0][ar] = a0.x; As[0][ak+1][ar] = a0.y;
        As[0][ak+2][ar] = a0.z; As[0][ak+3][ar] = a0.w;
        As[0][ak+4][ar] = a1.x; As[0][ak+5][ar] = a1.y;
        As[0][ak+6][ar] = a1.z; As[0][ak+7][ar] = a1.w;
        *(ulonglong2*)&Bs[0][bk][bn]     = make_ulonglong2(pack2(b0.x,b0.x), pack2(b0.y,b0.y));
        *(ulonglong2*)&Bs[0][bk][bn + 2] = make_ulonglong2(pack2(b0.z,b0.z), pack2(b0.w,b0.w));
    }
    __syncthreads();

    for (int k0 = 0; k0 < K; k0 += 16) {
        const int buf = (k0 >> 4) & 1;
        const int nxt = buf ^ 1;
        const bool more = (k0 + 16 < K);
        if (more) {
            const int kn = k0 + 16;
            const float* ap = &A[(size_t)(m0 + ar) * K + kn + ak];
            a0 = *(const float4*)(ap + 0);
            a1 = *(const float4*)(ap + 4);
            b0 = *(const float4*)&W[(size_t)(kn + bk) * N + n0 + bn];
        }

        #pragma unroll
        for (int kk = 0; kk < 16; kk++) {
            ulonglong2 a2  = *(const ulonglong2*)&As[buf][kk][tr * 4];
            ulonglong2 b01 = *(const ulonglong2*)&Bs[buf][kk][tcg * 8];
            ulonglong2 b23 = *(const ulonglong2*)&Bs[buf][kk][tcg * 8 + 2];
            ulonglong2 b45 = *(const ulonglong2*)&Bs[buf][kk][tcg * 8 + 4];
            ulonglong2 b67 = *(const ulonglong2*)&Bs[buf][kk][tcg * 8 + 6];
            u64 ap2[2] = {a2.x, a2.y};
            u64 bp[8]  = {b01.x, b01.y, b23.x, b23.y, b45.x, b45.y, b67.x, b67.y};
            #pragma unroll
            for (int i = 0; i < 2; i++)
                #pragma unroll
                for (int j = 0; j < 8; j++)
                    acc[i][j] = ffma2(ap2[i], bp[j], acc[i][j]);
        }

        if (more) {
            As[nxt][ak+0][ar] = a0.x; As[nxt][ak+1][ar] = a0.y;
            As[nxt][ak+2][ar] = a0.z; As[nxt][ak+3][ar] = a0.w;
            As[nxt][ak+4][ar] = a1.x; As[nxt][ak+5][ar] = a1.y;
            As[nxt][ak+6][ar] = a1.z; As[nxt][ak+7][ar] = a1.w;
            *(ulonglong2*)&Bs[nxt][bk][bn]     = make_ulonglong2(pack2(b0.x,b0.x), pack2(b0.y,b0.y));
            *(ulonglong2*)&Bs[nxt][bk][bn + 2] = make_ulonglong2(pack2(b0.z,b0.z), pack2(b0.w,b0.w));
        }
        __syncthreads();
    }

    float bias8[8];
    #pragma unroll
    for (int j = 0; j < 8; j++) bias8[j] = bias[n0 + tcg * 8 + j];

    #pragma unroll
    for (int p = 0; p < 2; p++) {
        float2 u[8];
        #pragma unroll
        for (int j = 0; j < 8; j++) u[j] = unpack2(acc[p][j]);
        const int row_lo = m0 + tr * 4 + 2 * p;
        float4 lo0 = make_float4(u[0].x + bias8[0], u[1].x + bias8[1],
                                 u[2].x + bias8[2], u[3].x + bias8[3]);
        float4 lo1 = make_float4(u[4].x + bias8[4], u[5].x + bias8[5],
                                 u[6].x + bias8[6], u[7].x + bias8[7]);
        float4 hi0 = make_float4(u[0].y + bias8[0], u[1].y + bias8[1],
                                 u[2].y + bias8[2], u[3].y + bias8[3]);
        float4 hi1 = make_float4(u[4].y + bias8[4], u[5].y + bias8[5],
                                 u[6].y + bias8[6], u[7].y + bias8[7]);
        *(float4*)&C[(size_t)row_lo * N + n0 + tcg * 8]           = lo0;
        *(float4*)&C[(size_t)row_lo * N + n0 + tcg * 8 + 4]       = lo1;
        *(float4*)&C[(size_t)(row_lo + 1) * N + n0 + tcg * 8]     = hi0;
        *(float4*)&C[(size_t)(row_lo + 1) * N + n0 + tcg * 8 + 4] = hi1;
    }
}

// ---------------------------------------------------------------------------
// Banded quadratic attention with f32x2 + duplicated-pair smem:
//   out_t = sum_{s<=t, t-s<window} gamma^(t-s) (q_t . k_s)^2 v_s
// ---------------------------------------------------------------------------
#define ATTN_SMEM (8192 + 16384 + 16384 + 16384)   // Qs + Ks2 + Vs2 + Ws = 56 KB

__global__ __launch_bounds__(128) void attn_kernel()
{
    extern __shared__ __align__(16) char smem[];
    float (*Qs)[64]  = (float (*)[64])(smem);                 // [32][64] floats
    u64   (*Ks2)[64] = (u64   (*)[64])(smem + 8192);          // [32][64] dup pairs
    u64   (*Vs2)[32] = (u64   (*)[32])(smem + 8192 + 16384);  // [64][32] dup pairs
    float (*Ws)[64]  = (float (*)[64])(smem + 8192 + 32768);  // [64][64]

    const int tid = threadIdx.x;
    const int bh = blockIdx.y;
    const int b  = bh >> 4;
    const int h  = bh & 15;
    const int t0 = blockIdx.x * 64;

    const int r = tid >> 1;
    const int c = (tid & 1) * 16;

    // load Q tile transposed (once per block)
    {
        const float* qp = &g_q[(size_t)(b * SEQ + t0 + r) * HID + h * HD + c];
        #pragma unroll
        for (int v = 0; v < 4; v++) {
            float4 q4 = *(const float4*)(qp + v * 4);
            Qs[c + v*4 + 0][r] = q4.x; Qs[c + v*4 + 1][r] = q4.y;
            Qs[c + v*4 + 2][r] = q4.z; Qs[c + v*4 + 3][r] = q4.w;
        }
    }

    const int tq  = tid >> 4;    // phase-1 q group (8 queries = 4 pairs)
    const int ts  = tid & 15;    // phase-1 s group (4)
    const int tq2 = tid & 15;    // phase-2 q group (4 queries = 2 pairs)
    const int td  = tid >> 4;    // phase-2 d group (4 dims)

    float gqv[8], ginv[4];
    #pragma unroll
    for (int u = 0; u < 8; u++) gqv[u] = exp2f((float)(tq * 8 + u) * LOG2G);
    #pragma unroll
    for (int j = 0; j < 4; j++) ginv[j] = exp2f((float)(-(ts * 4 + j)) * LOG2G);

    u64 op[2][4];
    #pragma unroll
    for (int i = 0; i < 2; i++)
        #pragma unroll
        for (int j = 0; j < 4; j++) op[i][j] = 0ull;

    const int lo  = t0 - WIN + 1;
    const int st0 = (lo > 0 ? lo : 0) >> 6;
    const int st1 = t0 >> 6;

    for (int st = st0; st <= st1; st++) {
        const int sbase = st * 64;
        {
            const float* kp = &g_k[(size_t)(b * SEQ + sbase + r) * HID + h * HD + c];
            #pragma unroll
            for (int v = 0; v < 4; v++) {
                float4 k4 = *(const float4*)(kp + v * 4);
                Ks2[c + v*4 + 0][r] = pack2(k4.x, k4.x);
                Ks2[c + v*4 + 1][r] = pack2(k4.y, k4.y);
                Ks2[c + v*4 + 2][r] = pack2(k4.z, k4.z);
                Ks2[c + v*4 + 3][r] = pack2(k4.w, k4.w);
            }
            const float* vp = &g_v[(size_t)(b * SEQ + sbase + r) * HID + h * HD + c];
            #pragma unroll
            for (int v = 0; v < 4; v++) {
                float4 v4 = *(const float4*)(vp + v * 4);
                *(ulonglong2*)&Vs2[r][c + v*4]     = make_ulonglong2(pack2(v4.x,v4.x), pack2(v4.y,v4.y));
                *(ulonglong2*)&Vs2[r][c + v*4 + 2] = make_ulonglong2(pack2(v4.z,v4.z), pack2(v4.w,v4.w));
            }
        }
        __syncthreads();

        // phase 1: scores, 4 q-pairs x 4 s per thread
        u64 sp[4][4];
        #pragma unroll
        for (int i = 0; i < 4; i++)
            #pragma unroll
            for (int j = 0; j < 4; j++) sp[i][j] = 0ull;

        #pragma unroll
        for (int d = 0; d < 32; d++) {
            ulonglong2 ql = *(const ulonglong2*)&Qs[d][tq * 8];
            ulonglong2 qh = *(const ulonglong2*)&Qs[d][tq * 8 + 4];
            ulonglong2 k2 = *(const ulonglong2*)&Ks2[d][ts * 4];
            ulonglong2 k3 = *(const ulonglong2*)&Ks2[d][ts * 4 + 2];
            u64 qp2[4] = {ql.x, ql.y, qh.x, qh.y};
            u64 kp2[4] = {k2.x, k2.y, k3.x, k3.y};
            #pragma unroll
            for (int i = 0; i < 4; i++)
                #pragma unroll
                for (int j = 0; j < 4; j++)
                    sp[i][j] = ffma2(qp2[i], kp2[j], sp[i][j]);
        }

        // weight + transposed store: w = s^2 * gamma^(q + (t0-sbase) - s)
        {
            const float gt = exp2f((float)(t0 - sbase) * LOG2G);
            float cq[8];
            #pragma unroll
            for (int u = 0; u < 8; u++) cq[u] = gqv[u] * gt;
            const bool diag = (st == st1);

            #pragma unroll
            for (int i = 0; i < 4; i++) {
                const int q_lo = tq * 8 + 2 * i;
                #pragma unroll
                for (int j = 0; j < 4; j++) {
                    const int sl = ts * 4 + j;
                    float2 sv = unpack2(sp[i][j]);
                    float w0 = sv.x * sv.x * cq[2*i]   * ginv[j];
                    float w1 = sv.y * sv.y * cq[2*i+1] * ginv[j];
                    if (diag) {
                        if (sl > q_lo)     w0 = 0.f;
                        if (sl > q_lo + 1) w1 = 0.f;
                    }
                    *(u64*)&Ws[sl][q_lo] = pack2(w0, w1);
                }
            }
        }
        __syncthreads();

        // phase 2: O += Ws^T V, 2 q-pairs x 4 dims per thread
        #pragma unroll 8
        for (int s2 = 0; s2 < 64; s2++) {
            ulonglong2 wp = *(const ulonglong2*)&Ws[s2][tq2 * 4];
            ulonglong2 v0 = *(const ulonglong2*)&Vs2[s2][td * 4];
            ulonglong2 v1 = *(const ulonglong2*)&Vs2[s2][td * 4 + 2];
            u64 wpp[2] = {wp.x, wp.y};
            u64 vp2[4] = {v0.x, v0.y, v1.x, v1.y};
            #pragma unroll
            for (int i = 0; i < 2; i++)
                #pragma unroll
                for (int j = 0; j < 4; j++)
                    op[i][j] = ffma2(wpp[i], vp2[j], op[i][j]);
        }
        __syncthreads();
    }

    #pragma unroll
    for (int i = 0; i < 2; i++) {
        float2 u[4];
        #pragma unroll
        for (int j = 0; j < 4; j++) u[j] = unpack2(op[i][j]);
        const int t_lo = t0 + tq2 * 4 + 2 * i;
        float4 olo = make_float4(u[0].x, u[1].x, u[2].x, u[3].x);
        float4 ohi = make_float4(u[0].y, u[1].y, u[2].y, u[3].y);
        *(float4*)&g_att[(size_t)(b * SEQ + t_lo) * HID + h * HD + td * 4]     = olo;
        *(float4*)&g_att[(size_t)(b * SEQ + t_lo + 1) * HID + h * HD + td * 4] = ohi;
    }
}

// ---------------------------------------------------------------------------
extern "C" void kernel_launch(void* const* d_in, const int* in_sizes, int n_in,
                              void* d_out, int out_size)
{
    const float* x  = (const float*)d_in[0];
    const float* qw = (const float*)d_in[1];
    const float* qb = (const float*)d_in[2];
    const float* kw = (const float*)d_in[3];
    const float* kb = (const float*)d_in[4];
    const float* vw = (const float*)d_in[5];
    const float* vb = (const float*)d_in[6];
    const float* ow = (const float*)d_in[7];
    const float* ob = (const float*)d_in[8];
    float* out = (float*)d_out;

    float *pq, *pk, *pv, *pa;
    cudaGetSymbolAddress((void**)&pq, g_q);
    cudaGetSymbolAddress((void**)&pk, g_k);
    cudaGetSymbolAddress((void**)&pv, g_v);
    cudaGetSymbolAddress((void**)&pa, g_att);

    cudaFuncSetAttribute(attn_kernel,
                         cudaFuncAttributeMaxDynamicSharedMemorySize, ATTN_SMEM);

    // fused QKV projections: 128x64 tiles, 128 threads, grid (8,16,3) = 384 blocks
    gemm_qkv_kernel<<<dim3(8, 16, 3), 128>>>(x, qw, qb, pq, kw, kb, pk, vw, vb, pv);
    // banded quadratic attention
    attn_kernel<<<dim3(SEQ / 64, BATCH * NH), 128, ATTN_SMEM>>>();
    // output projection: 128x64 tiles, 256 threads, grid (8,16) = 128 blocks
    gemm_o_kernel<<<dim3(8, 16), 256>>>(pa, ow, ob, out);
}